// round 1
// baseline (speedup 1.0000x reference)
#include <cuda_runtime.h>
#include <cuda_fp16.h>
#include <cstdint>

#define N_OUT 4096
#define M_IN  4096
#define BATCH 128
#define KTOT  4096
#define SPLITK 4
#define KPER  (KTOT / SPLITK)   // 1024
#define BK    64
#define NT    (KPER / BK)       // 16
#define BN    128

// Scratch (device globals; no allocation allowed)
__device__ __half g_Wh[(size_t)N_OUT * M_IN];        // 32MB dense fp16 weights
__device__ __half g_xh[2 * BATCH * M_IN];            // x split: [0]=hi, [1]=lo

// ---------------------------------------------------------------------------
// helpers
// ---------------------------------------------------------------------------
__device__ __forceinline__ uint32_t smem_u32(const void* p) {
    return (uint32_t)__cvta_generic_to_shared(p);
}

__device__ __forceinline__ void cpasync16(void* dst, const void* src) {
    uint32_t d = smem_u32(dst);
    asm volatile("cp.async.cg.shared.global [%0], [%1], 16;" :: "r"(d), "l"(src));
}

__device__ __forceinline__ void ldsm4(uint32_t* r, uint32_t a) {
    asm volatile("ldmatrix.sync.aligned.m8n8.x4.shared.b16 {%0,%1,%2,%3}, [%4];"
                 : "=r"(r[0]), "=r"(r[1]), "=r"(r[2]), "=r"(r[3]) : "r"(a));
}

__device__ __forceinline__ void ldsm2(uint32_t* r, uint32_t a) {
    asm volatile("ldmatrix.sync.aligned.m8n8.x2.shared.b16 {%0,%1}, [%2];"
                 : "=r"(r[0]), "=r"(r[1]) : "r"(a));
}

__device__ __forceinline__ void mma16816(float* c, const uint32_t* a, const uint32_t* b) {
    asm volatile(
        "mma.sync.aligned.m16n8k16.row.col.f32.f16.f16.f32 "
        "{%0,%1,%2,%3}, {%4,%5,%6,%7}, {%8,%9}, {%0,%1,%2,%3};"
        : "+f"(c[0]), "+f"(c[1]), "+f"(c[2]), "+f"(c[3])
        : "r"(a[0]), "r"(a[1]), "r"(a[2]), "r"(a[3]), "r"(b[0]), "r"(b[1]));
}

__device__ __forceinline__ void redv2(float* p, float x, float y) {
    asm volatile("red.global.add.v2.f32 [%0], {%1, %2};"
                 :: "l"(p), "f"(x), "f"(y) : "memory");
}

// ---------------------------------------------------------------------------
// K0: zero the dense weight matrix (32MB)
// ---------------------------------------------------------------------------
__global__ void k_zero() {
    uint4* p = reinterpret_cast<uint4*>(g_Wh);
    const int n4 = (int)(((size_t)N_OUT * M_IN) / 8);   // 8 halves per uint4
    uint4 z; z.x = 0; z.y = 0; z.z = 0; z.w = 0;
    int stride = gridDim.x * blockDim.x;
    for (int i = blockIdx.x * blockDim.x + threadIdx.x; i < n4; i += stride)
        p[i] = z;
}

// ---------------------------------------------------------------------------
// K1: split x into fp16 hi/lo, init out with bias (out poisoned 0xAA by harness)
// ---------------------------------------------------------------------------
__global__ void k_prep(const float* __restrict__ x,
                       const float* __restrict__ bias,
                       float* __restrict__ out) {
    int idx = blockIdx.x * blockDim.x + threadIdx.x;
    if (idx < BATCH * M_IN) {
        float v = x[idx];
        __half h = __float2half_rn(v);
        g_xh[idx] = h;
        g_xh[BATCH * M_IN + idx] = __float2half_rn(v - __half2float(h));
        // out is [BATCH, N_OUT]; BATCH*N_OUT == BATCH*M_IN here
        out[idx] = bias[idx & (N_OUT - 1)];
    }
}

// ---------------------------------------------------------------------------
// K2: scatter quantized values into dense fp16 W (duplicates must accumulate)
// ---------------------------------------------------------------------------
__global__ void k_scatter(const int* __restrict__ val,
                          const int* __restrict__ rows,
                          const int* __restrict__ cols,
                          int nnz) {
    int i = blockIdx.x * blockDim.x + threadIdx.x;
    if (i < nnz) {
        int r = rows[i];
        int c = cols[i];
        atomicAdd(&g_Wh[(size_t)r * M_IN + c], __float2half_rn((float)val[i]));
    }
}

// ---------------------------------------------------------------------------
// K3: GEMM  out[b, n] += scale[n] * sum_k (x_hi + x_lo)[b,k] * W[n,k]
// CTA tile: 128(M=batch) x 128(N), BK=64, split-K=4, cp.async double buffer.
// 8 warps: warp tile 64(M) x 32(N), mma.sync m16n8k16 fp16->fp32.
// smem: A/B tiles 128x64 halves each, 2 stages, XOR-swizzled (16B chunk ^ row%8)
// ---------------------------------------------------------------------------
__global__ void __launch_bounds__(256, 1)
k_gemm(const float* __restrict__ scales, float* __restrict__ out) {
    extern __shared__ __half sm[];   // [0..16KB)x2 = A stages, [32KB..64KB) = B stages

    const int tid  = threadIdx.x;
    const int lane = tid & 31;
    const int warp = tid >> 5;
    const int wm   = warp & 1;       // 0..1  -> 64-row M strip
    const int wn   = warp >> 1;      // 0..3  -> 32-col N strip
    const int bn0  = blockIdx.x * BN;
    const int kbase = blockIdx.y * KPER;

    float acc[4][4][4];
#pragma unroll
    for (int i = 0; i < 4; i++)
#pragma unroll
        for (int j = 0; j < 4; j++)
#pragma unroll
            for (int q = 0; q < 4; q++) acc[i][j][q] = 0.0f;

    // per-thread global->smem load coordinates (4 x 16B chunks for A, 4 for B)
    int qrow[4], qc[4];
#pragma unroll
    for (int i = 0; i < 4; i++) {
        int q = tid + i * 256;       // 0..1023 chunk id; 8 chunks per row
        qrow[i] = q >> 3;            // 0..127
        qc[i]   = q & 7;             // 0..7
    }

#pragma unroll 1
    for (int pass = 0; pass < 2; ++pass) {
        const __half* Ag = g_xh + pass * (BATCH * M_IN);

        // prefetch stage 0
        {
            const int k0 = kbase;
#pragma unroll
            for (int i = 0; i < 4; i++) {
                int sw = (qc[i] ^ (qrow[i] & 7)) << 3;
                cpasync16(sm + qrow[i] * 64 + sw,
                          Ag + qrow[i] * M_IN + k0 + (qc[i] << 3));
                cpasync16(sm + 16384 + qrow[i] * 64 + sw,
                          g_Wh + (size_t)(bn0 + qrow[i]) * M_IN + k0 + (qc[i] << 3));
            }
            asm volatile("cp.async.commit_group;");
        }

#pragma unroll 1
        for (int kt = 0; kt < NT; ++kt) {
            asm volatile("cp.async.wait_group 0;");
            __syncthreads();

            const int s = kt & 1;
            if (kt + 1 < NT) {
                const int k0 = kbase + (kt + 1) * BK;
                const int s2 = (kt + 1) & 1;
#pragma unroll
                for (int i = 0; i < 4; i++) {
                    int sw = (qc[i] ^ (qrow[i] & 7)) << 3;
                    cpasync16(sm + s2 * 8192 + qrow[i] * 64 + sw,
                              Ag + qrow[i] * M_IN + k0 + (qc[i] << 3));
                    cpasync16(sm + 16384 + s2 * 8192 + qrow[i] * 64 + sw,
                              g_Wh + (size_t)(bn0 + qrow[i]) * M_IN + k0 + (qc[i] << 3));
                }
                asm volatile("cp.async.commit_group;");
            }

            const __half* As = sm + s * 8192;
            const __half* Bs = sm + 16384 + s * 8192;

#pragma unroll
            for (int ks = 0; ks < 4; ++ks) {
                uint32_t af[4][4];
#pragma unroll
                for (int mi = 0; mi < 4; mi++) {
                    int row = wm * 64 + mi * 16 + (lane & 7) + ((lane >> 3) & 1) * 8;
                    int ch  = ks * 2 + (lane >> 4);
                    ldsm4(af[mi], smem_u32(As + row * 64 + ((ch ^ (row & 7)) << 3)));
                }
#pragma unroll
                for (int ni = 0; ni < 4; ni++) {
                    int rowb = wn * 32 + ni * 8 + (lane & 7);
                    int chb  = ks * 2 + ((lane >> 3) & 1);
                    uint32_t bf[2];
                    ldsm2(bf, smem_u32(Bs + rowb * 64 + ((chb ^ (rowb & 7)) << 3)));
#pragma unroll
                    for (int mi = 0; mi < 4; mi++)
                        mma16816(acc[mi][ni], af[mi], bf);
                }
            }
            __syncthreads();
        }
    }

    // epilogue: scale by per-row weight scale, atomically add into bias-init out
#pragma unroll
    for (int mi = 0; mi < 4; mi++) {
#pragma unroll
        for (int ni = 0; ni < 4; ni++) {
            int r0 = wm * 64 + mi * 16 + (lane >> 2);            // batch row
            int nq = bn0 + wn * 32 + ni * 8 + ((lane & 3) << 1); // output col
            float s0 = __ldg(scales + nq);
            float s1 = __ldg(scales + nq + 1);
            redv2(out + (size_t)r0 * N_OUT + nq,
                  acc[mi][ni][0] * s0, acc[mi][ni][1] * s1);
            redv2(out + (size_t)(r0 + 8) * N_OUT + nq,
                  acc[mi][ni][2] * s0, acc[mi][ni][3] * s1);
        }
    }
}

// ---------------------------------------------------------------------------
extern "C" void kernel_launch(void* const* d_in, const int* in_sizes, int n_in,
                              void* d_out, int out_size) {
    const float* x    = (const float*)d_in[0];
    const int*   wval = (const int*)d_in[1];
    const float* wsc  = (const float*)d_in[2];
    const int*   rows = (const int*)d_in[3];
    const int*   cols = (const int*)d_in[4];
    const float* bias = (const float*)d_in[5];
    float* out = (float*)d_out;
    const int nnz = in_sizes[1];

    cudaFuncSetAttribute(k_gemm, cudaFuncAttributeMaxDynamicSharedMemorySize, 65536);

    k_zero<<<1024, 256>>>();
    k_prep<<<(BATCH * M_IN + 255) / 256, 256>>>(x, bias, out);
    k_scatter<<<(nnz + 255) / 256, 256>>>(wval, rows, cols, nnz);
    k_gemm<<<dim3(N_OUT / BN, SPLITK), 256, 65536>>>(wsc, out);
}

// round 4
// speedup vs baseline: 1.3073x; 1.3073x over previous
#include <cuda_runtime.h>
#include <cuda_fp16.h>
#include <cstdint>

#define N_OUT 4096
#define M_IN  4096
#define BATCH 128
#define KTOT  4096
#define BN    64
#define SPLITK 4
#define KPER  (KTOT / SPLITK)   // 1024
#define BK    64
#define KT    (KPER / BK)       // 16
#define STAGES 4
// stage size in halves: A 128x64 + B 64x64 = 12288 halves (24KB)
#define STG_H 12288
#define SMEM_BYTES (STAGES * STG_H * 2)   // 98304

// Scratch (device globals; no allocation allowed)
__device__ __align__(16) __half g_Wh[(size_t)N_OUT * M_IN];   // 32MB dense fp16 W
__device__ __align__(16) __half g_xh[BATCH * M_IN];           // x in fp16

// ---------------------------------------------------------------------------
__device__ __forceinline__ uint32_t smem_u32(const void* p) {
    return (uint32_t)__cvta_generic_to_shared(p);
}
__device__ __forceinline__ void cpasync16(uint32_t dst, const void* src) {
    asm volatile("cp.async.cg.shared.global [%0], [%1], 16;" :: "r"(dst), "l"(src));
}
__device__ __forceinline__ void ldsm4(uint32_t* r, uint32_t a) {
    asm volatile("ldmatrix.sync.aligned.m8n8.x4.shared.b16 {%0,%1,%2,%3}, [%4];"
                 : "=r"(r[0]), "=r"(r[1]), "=r"(r[2]), "=r"(r[3]) : "r"(a));
}
__device__ __forceinline__ void ldsm2(uint32_t* r, uint32_t a) {
    asm volatile("ldmatrix.sync.aligned.m8n8.x2.shared.b16 {%0,%1}, [%2];"
                 : "=r"(r[0]), "=r"(r[1]) : "r"(a));
}
__device__ __forceinline__ void mma16816(float* c, const uint32_t* a, const uint32_t* b) {
    asm volatile(
        "mma.sync.aligned.m16n8k16.row.col.f32.f16.f16.f32 "
        "{%0,%1,%2,%3}, {%4,%5,%6,%7}, {%8,%9}, {%0,%1,%2,%3};"
        : "+f"(c[0]), "+f"(c[1]), "+f"(c[2]), "+f"(c[3])
        : "r"(a[0]), "r"(a[1]), "r"(a[2]), "r"(a[3]), "r"(b[0]), "r"(b[1]));
}
__device__ __forceinline__ void redv2(float* p, float x, float y) {
    asm volatile("red.global.add.v2.f32 [%0], {%1, %2};"
                 :: "l"(p), "f"(x), "f"(y) : "memory");
}

// ---------------------------------------------------------------------------
// K0 (fused): zero W, convert x -> fp16, init out with bias
// ---------------------------------------------------------------------------
__global__ void k_prep(const float* __restrict__ x,
                       const float* __restrict__ bias,
                       float* __restrict__ out) {
    const int gid = blockIdx.x * blockDim.x + threadIdx.x;
    const int nthr = gridDim.x * blockDim.x;

    // zero W: 2,097,152 uint4 chunks, grid-stride
    uint4* wp = reinterpret_cast<uint4*>(g_Wh);
    uint4 z; z.x = 0; z.y = 0; z.z = 0; z.w = 0;
    const int n4 = (int)(((size_t)N_OUT * M_IN) / 8);
    for (int i = gid; i < n4; i += nthr) wp[i] = z;

    // x conversion + out=bias: 4 elements per thread, first 131072 threads
    if (gid < (BATCH * M_IN) / 4) {
        const int idx = gid * 4;
        float4 v = *reinterpret_cast<const float4*>(x + idx);
        __half2* xp = reinterpret_cast<__half2*>(g_xh + idx);
        xp[0] = __floats2half2_rn(v.x, v.y);
        xp[1] = __floats2half2_rn(v.z, v.w);
        *reinterpret_cast<float4*>(out + idx) =
            *reinterpret_cast<const float4*>(bias + (idx & (N_OUT - 1)));
    }
}

// ---------------------------------------------------------------------------
// K1: scatter quantized values into dense fp16 W (duplicates accumulate)
// ---------------------------------------------------------------------------
__global__ void k_scatter(const int* __restrict__ val,
                          const int* __restrict__ rows,
                          const int* __restrict__ cols,
                          int nnz) {
    int i = blockIdx.x * blockDim.x + threadIdx.x;
    if (i < nnz) {
        atomicAdd(&g_Wh[(size_t)rows[i] * M_IN + cols[i]],
                  __float2half_rn((float)val[i]));
    }
}

// ---------------------------------------------------------------------------
// K2: GEMM  out[b,n] += scale[n] * sum_k x_h[b,k] * W[n,k]
// CTA tile 128(batch) x 64(N), BK=64, 4-stage cp.async, split-K=4.
// 8 warps as 4(m) x 2(n); warp tile 32x32 (mi<2 x ni<4 of m16n8k16).
// smem per stage: A[128][64] then B[64][64], rows of 64 halves,
// 16B chunk c of row r stored at column chunk (c ^ (r&7)).
// ---------------------------------------------------------------------------
__global__ void __launch_bounds__(256, 2)
k_gemm(const float* __restrict__ scales, float* __restrict__ out) {
    extern __shared__ __align__(1024) __half sm[];

    const int tid  = threadIdx.x;
    const int lane = tid & 31;
    const int warp = tid >> 5;
    const int wm   = warp & 3;       // 0..3  -> 32-row M strip
    const int wn   = warp >> 2;      // 0..1  -> 32-col N strip
    const int bn0  = blockIdx.x * BN;
    const int kbase = blockIdx.y * KPER;

    float acc[2][4][4];
#pragma unroll
    for (int i = 0; i < 2; i++)
#pragma unroll
        for (int j = 0; j < 4; j++)
#pragma unroll
            for (int q = 0; q < 4; q++) acc[i][j][q] = 0.0f;

    // per-thread load coords: 4 A chunks, 2 B chunks of 16B each
    uint32_t aoff[4], boff[2];
    const __half* asrc[4];
    const __half* bsrc[2];
#pragma unroll
    for (int i = 0; i < 4; i++) {
        int q = tid + i * 256;           // 0..1023
        int r = q >> 3, c = q & 7;
        aoff[i] = (r * 64 + ((c ^ (r & 7)) << 3)) * 2;   // byte offset
        asrc[i] = g_xh + r * M_IN + kbase + (c << 3);
    }
#pragma unroll
    for (int i = 0; i < 2; i++) {
        int q = tid + i * 256;           // 0..511
        int r = q >> 3, c = q & 7;
        boff[i] = (8192 + r * 64 + ((c ^ (r & 7)) << 3)) * 2;
        bsrc[i] = g_Wh + (size_t)(bn0 + r) * M_IN + kbase + (c << 3);
    }

    const uint32_t smb = smem_u32(sm);

    auto load_stage = [&](int s, int kofs) {
        uint32_t sb = smb + s * (STG_H * 2);
#pragma unroll
        for (int i = 0; i < 4; i++) cpasync16(sb + aoff[i], asrc[i] + kofs);
#pragma unroll
        for (int i = 0; i < 2; i++) cpasync16(sb + boff[i], bsrc[i] + kofs);
    };

    // prologue: stages 0..2
#pragma unroll
    for (int s = 0; s < STAGES - 1; s++) {
        load_stage(s, s * BK);
        asm volatile("cp.async.commit_group;");
    }

#pragma unroll 1
    for (int kt = 0; kt < KT; ++kt) {
        asm volatile("cp.async.wait_group %0;" :: "n"(STAGES - 2));
        __syncthreads();

        // issue loads for kt+3 (always commit to keep group count uniform)
        if (kt + STAGES - 1 < KT)
            load_stage((kt + STAGES - 1) & (STAGES - 1), (kt + STAGES - 1) * BK);
        asm volatile("cp.async.commit_group;");

        const __half* As = sm + (kt & (STAGES - 1)) * STG_H;
        const __half* Bs = As + 8192;

#pragma unroll
        for (int ks = 0; ks < 4; ++ks) {
            uint32_t af[2][4];
#pragma unroll
            for (int mi = 0; mi < 2; mi++) {
                int row = wm * 32 + mi * 16 + (lane & 7) + ((lane >> 3) & 1) * 8;
                int ch  = ks * 2 + (lane >> 4);
                ldsm4(af[mi], smem_u32(As + row * 64 + ((ch ^ (row & 7)) << 3)));
            }
#pragma unroll
            for (int ni = 0; ni < 4; ni++) {
                int rowb = wn * 32 + ni * 8 + (lane & 7);
                int chb  = ks * 2 + ((lane >> 3) & 1);
                uint32_t bf[2];
                ldsm2(bf, smem_u32(Bs + rowb * 64 + ((chb ^ (rowb & 7)) << 3)));
#pragma unroll
                for (int mi = 0; mi < 2; mi++)
                    mma16816(acc[mi][ni], af[mi], bf);
            }
        }
    }

    // epilogue: scale + atomic add into bias-initialized out
#pragma unroll
    for (int ni = 0; ni < 4; ni++) {
        int nq = bn0 + wn * 32 + ni * 8 + ((lane & 3) << 1);
        float s0 = __ldg(scales + nq);
        float s1 = __ldg(scales + nq + 1);
#pragma unroll
        for (int mi = 0; mi < 2; mi++) {
            int r0 = wm * 32 + mi * 16 + (lane >> 2);
            redv2(out + (size_t)r0 * N_OUT + nq,
                  acc[mi][ni][0] * s0, acc[mi][ni][1] * s1);
            redv2(out + (size_t)(r0 + 8) * N_OUT + nq,
                  acc[mi][ni][2] * s0, acc[mi][ni][3] * s1);
        }
    }
}

// ---------------------------------------------------------------------------
extern "C" void kernel_launch(void* const* d_in, const int* in_sizes, int n_in,
                              void* d_out, int out_size) {
    const float* x    = (const float*)d_in[0];
    const int*   wval = (const int*)d_in[1];
    const float* wsc  = (const float*)d_in[2];
    const int*   rows = (const int*)d_in[3];
    const int*   cols = (const int*)d_in[4];
    const float* bias = (const float*)d_in[5];
    float* out = (float*)d_out;
    const int nnz = in_sizes[1];

    cudaFuncSetAttribute(k_gemm, cudaFuncAttributeMaxDynamicSharedMemorySize, SMEM_BYTES);

    k_prep<<<2048, 256>>>(x, bias, out);
    k_scatter<<<(nnz + 255) / 256, 256>>>(wval, rows, cols, nnz);
    k_gemm<<<dim3(N_OUT / BN, SPLITK), 256, SMEM_BYTES>>>(wsc, out);
}